// round 2
// baseline (speedup 1.0000x reference)
#include <cuda_runtime.h>
#include <math.h>

#define N_EXP 8
#define CDIM  1024
#define MAX_T 8192
#define NCH   256   // rank-scan chunks

// scratch (no allocation allowed -> __device__ globals)
__device__ float g_p1[MAX_T];
__device__ float g_p2[MAX_T];
__device__ int   g_e1[MAX_T];
__device__ int   g_e2[MAX_T];
__device__ int   g_r1[MAX_T];
__device__ int   g_r2[MAX_T];

// ---------------------------------------------------------------------------
// Kernel 1: gating GEMV + top-2 + masked softmax.
// 8 warps/block, warp per token. wg staged in shared, float4 x loads.
// ---------------------------------------------------------------------------
__global__ void gate_kernel(const float* __restrict__ x,
                            const float* __restrict__ wg,
                            int T)
{
    __shared__ float wgs[N_EXP * CDIM];   // 32 KB

    // cooperative load of wg into smem (float4, coalesced)
    {
        const float4* src = (const float4*)wg;
        float4*       dst = (float4*)wgs;
        for (int i = threadIdx.x; i < N_EXP * CDIM / 4; i += blockDim.x)
            dst[i] = src[i];
    }
    __syncthreads();

    int warp  = threadIdx.x >> 5;
    int lane  = threadIdx.x & 31;
    int token = blockIdx.x * 8 + warp;
    if (token >= T) return;

    const float4* xr = (const float4*)(x + (size_t)token * CDIM);

    float acc[N_EXP];
#pragma unroll
    for (int e = 0; e < N_EXP; e++) acc[e] = 0.f;

#pragma unroll
    for (int it = 0; it < CDIM / 128; it++) {          // 8 iterations
        int c4 = it * 32 + lane;                       // float4 index
        float4 xv = xr[c4];
#pragma unroll
        for (int e = 0; e < N_EXP; e++) {
            float4 w = *(const float4*)&wgs[e * CDIM + c4 * 4];
            acc[e] += xv.x * w.x + xv.y * w.y + xv.z * w.z + xv.w * w.w;
        }
    }
#pragma unroll
    for (int e = 0; e < N_EXP; e++) {
#pragma unroll
        for (int o = 16; o > 0; o >>= 1)
            acc[e] += __shfl_xor_sync(0xffffffffu, acc[e], o);
    }

    if (lane == 0) {
        // top-1 (first max on ties, matching lax.top_k)
        int e1 = 0; float l1 = acc[0];
#pragma unroll
        for (int e = 1; e < N_EXP; e++)
            if (acc[e] > l1) { l1 = acc[e]; e1 = e; }
        int e2 = -1; float l2 = -INFINITY;
#pragma unroll
        for (int e = 0; e < N_EXP; e++)
            if (e != e1 && acc[e] > l2) { l2 = acc[e]; e2 = e; }

        float p1 = 1.f / (1.f + expf(l2 - l1));   // stable: l2 <= l1
        float p2 = 1.f - p1;

        g_e1[token] = e1; g_e2[token] = e2;
        g_p1[token] = p1; g_p2[token] = p2;
    }
}

// ---------------------------------------------------------------------------
// Kernel 2: k-major cumulative ranks + used_capacity. One block, 256 threads.
// Chunked count -> warp-per-expert exclusive scan -> per-chunk rank assign.
// Ordering: all k=0 assignments (token order), then all k=1 assignments.
// ---------------------------------------------------------------------------
__global__ void rank_kernel(int T, int cap, float* __restrict__ out_used)
{
    __shared__ int s1[NCH][N_EXP + 1];
    __shared__ int s2[NCH][N_EXP + 1];
    __shared__ int tot1[N_EXP], tot2[N_EXP];

    int tid  = threadIdx.x;
    int per  = (T + NCH - 1) / NCH;
    int base = tid * per;
    int end  = min(base + per, T);

    int c1[N_EXP], c2[N_EXP];
#pragma unroll
    for (int e = 0; e < N_EXP; e++) { c1[e] = 0; c2[e] = 0; }
    for (int t = base; t < end; t++) { c1[g_e1[t]]++; c2[g_e2[t]]++; }
#pragma unroll
    for (int e = 0; e < N_EXP; e++) { s1[tid][e] = c1[e]; s2[tid][e] = c2[e]; }
    __syncthreads();

    // warp w performs exclusive scan over the 256 chunk-counts of expert w
    int wid = tid >> 5, lane = tid & 31;
    if (wid < N_EXP) {
        int v1[8], v2[8];
        int sum1 = 0, sum2 = 0;
#pragma unroll
        for (int j = 0; j < 8; j++) {
            int idx = lane * 8 + j;
            v1[j] = sum1; sum1 += s1[idx][wid];
            v2[j] = sum2; sum2 += s2[idx][wid];
        }
        // warp inclusive scan of per-lane sums
        int inc1 = sum1, inc2 = sum2;
#pragma unroll
        for (int o = 1; o < 32; o <<= 1) {
            int a = __shfl_up_sync(0xffffffffu, inc1, o);
            int b = __shfl_up_sync(0xffffffffu, inc2, o);
            if (lane >= o) { inc1 += a; inc2 += b; }
        }
        int exc1 = inc1 - sum1, exc2 = inc2 - sum2;
#pragma unroll
        for (int j = 0; j < 8; j++) {
            int idx = lane * 8 + j;
            s1[idx][wid] = exc1 + v1[j];
            s2[idx][wid] = exc2 + v2[j];
        }
        if (lane == 31) { tot1[wid] = inc1; tot2[wid] = inc2; }
    }
    __syncthreads();

    if (tid < N_EXP)
        out_used[tid] = (float)min(tot1[tid] + tot2[tid], cap);

    int o1[N_EXP], o2[N_EXP];
#pragma unroll
    for (int e = 0; e < N_EXP; e++) {
        o1[e] = s1[tid][e];
        o2[e] = tot1[e] + s2[tid][e];     // k=1 ranks start after all k=0
    }
    for (int t = base; t < end; t++) {
        int e = g_e1[t]; g_r1[t] = o1[e]; o1[e]++;
        e     = g_e2[t]; g_r2[t] = o2[e]; o2[e]++;
    }
}

// ---------------------------------------------------------------------------
// Kernel 3: fused zero-fill + scatter. One block per token row.
// Streams zeros (st.128) through cb and mask rows, injecting the token's
// <=2 (weight, mask) values in-line. Single pass over the 537 MB output.
// ---------------------------------------------------------------------------
__global__ void fill_kernel(float* __restrict__ cb,
                            float* __restrict__ mask,
                            int cap)
{
    int t = blockIdx.x;
    size_t row = (size_t)t * N_EXP * cap;
    float4* cb4 = (float4*)(cb + row);
    float4* mk4 = (float4*)(mask + row);
    int n4 = N_EXP * cap / 4;

    int   r1 = g_r1[t], r2 = g_r2[t];
    float p1 = g_p1[t], p2 = g_p2[t];
    int s1 = (r1 < cap) ? g_e1[t] * cap + r1 : -4;
    int s2 = (r2 < cap) ? g_e2[t] * cap + r2 : -4;
    int q1 = s1 >> 2, q2 = s2 >> 2;   // negative -> never matches

    for (int i = threadIdx.x; i < n4; i += blockDim.x) {
        float4 v = make_float4(0.f, 0.f, 0.f, 0.f);
        float4 m = make_float4(0.f, 0.f, 0.f, 0.f);
        if (i == q1) {
            ((float*)&v)[s1 & 3] = p1;
            ((float*)&m)[s1 & 3] = (p1 != 0.f) ? 1.f : 0.f;
        }
        if (i == q2) {
            ((float*)&v)[s2 & 3] = p2;
            ((float*)&m)[s2 & 3] = (p2 != 0.f) ? 1.f : 0.f;
        }
        cb4[i] = v;
        mk4[i] = m;
    }
}

// ---------------------------------------------------------------------------
extern "C" void kernel_launch(void* const* d_in, const int* in_sizes, int n_in,
                              void* d_out, int out_size)
{
    const float* x  = (const float*)d_in[0];
    const float* wg = (const float*)d_in[1];

    int T = in_sizes[0] / CDIM;                       // 4096
    // out layout: [used_capacity(8) | cb_weight(T*E*cap) | sec_mask(T*E*cap)]
    long long rest = (long long)out_size - N_EXP;
    int cap = (int)(rest / (2LL * T * N_EXP));        // 2048

    float* out_used = (float*)d_out;
    float* cb       = out_used + N_EXP;
    float* mask     = cb + (size_t)T * N_EXP * cap;

    gate_kernel<<<(T + 7) / 8, 256>>>(x, wg, T);
    rank_kernel<<<1, NCH>>>(T, cap, out_used);
    fill_kernel<<<T, 256>>>(cb, mask, cap);
}

// round 3
// speedup vs baseline: 1.3025x; 1.3025x over previous
#include <cuda_runtime.h>
#include <math.h>

#define N_EXP 8
#define CDIM  1024
#define MAX_T 8192
#define NCH   256    // rank-scan chunks (threads in rank kernel)
#define NGATE_BLOCKS(T) (((T) + 7) / 8)
#define NFILL 2048   // fill blocks

// scratch (no allocation allowed -> __device__ globals)
__device__ float g_p1[MAX_T];
__device__ float g_p2[MAX_T];
__device__ int   g_e1[MAX_T];
__device__ int   g_e2[MAX_T];

// ---------------------------------------------------------------------------
// Kernel 1 (fused): blocks [0, ngate) do gating GEMV + top-2 + softmax;
// blocks [ngate, ngate+NFILL) zero-fill the whole output flat.
// Gate work (~12us) hides entirely under the ~120us fill.
// ---------------------------------------------------------------------------
__global__ void fused_gate_fill_kernel(const float* __restrict__ x,
                                       const float* __restrict__ wg,
                                       float* __restrict__ out,
                                       int T, size_t out_elems, int ngate)
{
    if ((int)blockIdx.x >= ngate) {
        // ------------------ flat zero-fill ------------------
        size_t n4     = out_elems >> 2;
        size_t idx    = (size_t)(blockIdx.x - ngate) * blockDim.x + threadIdx.x;
        size_t stride = (size_t)NFILL * blockDim.x;
        float4* o4 = (float4*)out;
        const float4 z = make_float4(0.f, 0.f, 0.f, 0.f);

        size_t i = idx;
        // unrolled main loop: 4 independent stores in flight
        for (; i + 3 * stride < n4; i += 4 * stride) {
            o4[i]              = z;
            o4[i + stride]     = z;
            o4[i + 2 * stride] = z;
            o4[i + 3 * stride] = z;
        }
        for (; i < n4; i += stride) o4[i] = z;

        // scalar tail (out_elems not multiple of 4)
        if (blockIdx.x == (unsigned)ngate) {
            size_t tail = n4 << 2;
            size_t rem  = out_elems - tail;
            if (threadIdx.x < rem) out[tail + threadIdx.x] = 0.f;
        }
        return;
    }

    // ------------------ gating (warp per token) ------------------
    __shared__ float wgs[N_EXP * CDIM];   // 32 KB
    {
        const float4* src = (const float4*)wg;
        float4*       dst = (float4*)wgs;
        for (int i = threadIdx.x; i < N_EXP * CDIM / 4; i += blockDim.x)
            dst[i] = src[i];
    }
    __syncthreads();

    int warp  = threadIdx.x >> 5;
    int lane  = threadIdx.x & 31;
    int token = blockIdx.x * 8 + warp;
    if (token >= T) return;

    const float4* xr = (const float4*)(x + (size_t)token * CDIM);

    float acc[N_EXP];
#pragma unroll
    for (int e = 0; e < N_EXP; e++) acc[e] = 0.f;

#pragma unroll
    for (int it = 0; it < CDIM / 128; it++) {          // 8 iterations
        int c4 = it * 32 + lane;
        float4 xv = xr[c4];
#pragma unroll
        for (int e = 0; e < N_EXP; e++) {
            float4 w = *(const float4*)&wgs[e * CDIM + c4 * 4];
            acc[e] += xv.x * w.x + xv.y * w.y + xv.z * w.z + xv.w * w.w;
        }
    }
#pragma unroll
    for (int e = 0; e < N_EXP; e++) {
#pragma unroll
        for (int o = 16; o > 0; o >>= 1)
            acc[e] += __shfl_xor_sync(0xffffffffu, acc[e], o);
    }

    if (lane == 0) {
        int e1 = 0; float l1 = acc[0];
#pragma unroll
        for (int e = 1; e < N_EXP; e++)
            if (acc[e] > l1) { l1 = acc[e]; e1 = e; }
        int e2 = -1; float l2 = -INFINITY;
#pragma unroll
        for (int e = 0; e < N_EXP; e++)
            if (e != e1 && acc[e] > l2) { l2 = acc[e]; e2 = e; }

        float p1 = 1.f / (1.f + expf(l2 - l1));   // stable: l2 <= l1
        float p2 = 1.f - p1;

        g_e1[token] = e1; g_e2[token] = e2;
        g_p1[token] = p1; g_p2[token] = p2;
    }
}

// ---------------------------------------------------------------------------
// Kernel 2: k-major cumulative ranks + used_capacity + direct scatter.
// One block, 256 threads. Chunk counts -> warp-per-expert exclusive scan ->
// per-chunk rank replay writing the <=2 (weight, mask) values per token.
// ---------------------------------------------------------------------------
__global__ void rank_scatter_kernel(int T, int cap,
                                    float* __restrict__ out_used,
                                    float* __restrict__ cb,
                                    float* __restrict__ mask)
{
    __shared__ int s1[NCH][N_EXP + 1];
    __shared__ int s2[NCH][N_EXP + 1];
    __shared__ int tot1[N_EXP], tot2[N_EXP];

    int tid  = threadIdx.x;
    int per  = (T + NCH - 1) / NCH;
    int base = tid * per;
    int end  = min(base + per, T);

    int c1[N_EXP], c2[N_EXP];
#pragma unroll
    for (int e = 0; e < N_EXP; e++) { c1[e] = 0; c2[e] = 0; }
    for (int t = base; t < end; t++) { c1[g_e1[t]]++; c2[g_e2[t]]++; }
#pragma unroll
    for (int e = 0; e < N_EXP; e++) { s1[tid][e] = c1[e]; s2[tid][e] = c2[e]; }
    __syncthreads();

    // warp w: exclusive scan over the 256 chunk-counts of expert w
    int wid = tid >> 5, lane = tid & 31;
    if (wid < N_EXP) {
        int v1[8], v2[8];
        int sum1 = 0, sum2 = 0;
#pragma unroll
        for (int j = 0; j < 8; j++) {
            int idx = lane * 8 + j;
            v1[j] = sum1; sum1 += s1[idx][wid];
            v2[j] = sum2; sum2 += s2[idx][wid];
        }
        int inc1 = sum1, inc2 = sum2;
#pragma unroll
        for (int o = 1; o < 32; o <<= 1) {
            int a = __shfl_up_sync(0xffffffffu, inc1, o);
            int b = __shfl_up_sync(0xffffffffu, inc2, o);
            if (lane >= o) { inc1 += a; inc2 += b; }
        }
        int exc1 = inc1 - sum1, exc2 = inc2 - sum2;
#pragma unroll
        for (int j = 0; j < 8; j++) {
            int idx = lane * 8 + j;
            s1[idx][wid] = exc1 + v1[j];
            s2[idx][wid] = exc2 + v2[j];
        }
        if (lane == 31) { tot1[wid] = inc1; tot2[wid] = inc2; }
    }
    __syncthreads();

    if (tid < N_EXP)
        out_used[tid] = (float)min(tot1[tid] + tot2[tid], cap);

    int o1[N_EXP], o2[N_EXP];
#pragma unroll
    for (int e = 0; e < N_EXP; e++) {
        o1[e] = s1[tid][e];
        o2[e] = tot1[e] + s2[tid][e];     // k=1 ranks start after all k=0
    }
    for (int t = base; t < end; t++) {
        size_t row = (size_t)t * N_EXP * cap;
        int e = g_e1[t]; int r = o1[e]++;
        if (r < cap) {
            float p = g_p1[t];
            size_t o = row + (size_t)e * cap + r;
            cb[o] = p;
            if (p != 0.f) mask[o] = 1.f;
        }
        e = g_e2[t]; r = o2[e]++;
        if (r < cap) {
            float p = g_p2[t];
            size_t o = row + (size_t)e * cap + r;
            cb[o] = p;
            if (p != 0.f) mask[o] = 1.f;
        }
    }
}

// ---------------------------------------------------------------------------
extern "C" void kernel_launch(void* const* d_in, const int* in_sizes, int n_in,
                              void* d_out, int out_size)
{
    const float* x  = (const float*)d_in[0];
    const float* wg = (const float*)d_in[1];

    int T = in_sizes[0] / CDIM;                       // 4096
    // out layout: [used_capacity(8) | cb_weight(T*E*cap) | sec_mask(T*E*cap)]
    long long rest = (long long)out_size - N_EXP;
    int cap = (int)(rest / (2LL * T * N_EXP));        // 2048

    float* out_used = (float*)d_out;
    float* cb       = out_used + N_EXP;
    float* mask     = cb + (size_t)T * N_EXP * cap;

    int ngate = NGATE_BLOCKS(T);
    fused_gate_fill_kernel<<<ngate + NFILL, 256>>>(
        x, wg, (float*)d_out, T, (size_t)out_size, ngate);

    rank_scatter_kernel<<<1, NCH>>>(T, cap, out_used, cb, mask);
}

// round 4
// speedup vs baseline: 1.4724x; 1.1304x over previous
#include <cuda_runtime.h>
#include <math.h>

#define N_EXP 8
#define CDIM  1024
#define MAX_T 8192
#define NCH   256    // rank-scan chunks (threads in rank kernel)
#define NFILL 2048   // fill blocks

// scratch (no allocation allowed -> __device__ globals)
__device__ float g_p1[MAX_T];
__device__ float g_p2[MAX_T];
__device__ int   g_e1[MAX_T];
__device__ int   g_e2[MAX_T];
__device__ int   g_r1[MAX_T];
__device__ int   g_r2[MAX_T];

// ---------------------------------------------------------------------------
// Kernel 1 (fused): blocks [0, ngate) do gating GEMV + top-2 + softmax;
// blocks [ngate, ngate+NFILL) zero-fill the whole output flat.
// Gate work (~12us) hides entirely under the ~90us fill.
// ---------------------------------------------------------------------------
__global__ void fused_gate_fill_kernel(const float* __restrict__ x,
                                       const float* __restrict__ wg,
                                       float* __restrict__ out,
                                       int T, size_t out_elems, int ngate)
{
    if ((int)blockIdx.x >= ngate) {
        // ------------------ flat zero-fill ------------------
        size_t n4     = out_elems >> 2;
        size_t idx    = (size_t)(blockIdx.x - ngate) * blockDim.x + threadIdx.x;
        size_t stride = (size_t)NFILL * blockDim.x;
        float4* o4 = (float4*)out;
        const float4 z = make_float4(0.f, 0.f, 0.f, 0.f);

        size_t i = idx;
        for (; i + 3 * stride < n4; i += 4 * stride) {
            o4[i]              = z;
            o4[i + stride]     = z;
            o4[i + 2 * stride] = z;
            o4[i + 3 * stride] = z;
        }
        for (; i < n4; i += stride) o4[i] = z;

        // scalar tail (out_elems not multiple of 4)
        if (blockIdx.x == (unsigned)ngate) {
            size_t tail = n4 << 2;
            size_t rem  = out_elems - tail;
            if (threadIdx.x < rem) out[tail + threadIdx.x] = 0.f;
        }
        return;
    }

    // ------------------ gating (warp per token) ------------------
    __shared__ float wgs[N_EXP * CDIM];   // 32 KB
    {
        const float4* src = (const float4*)wg;
        float4*       dst = (float4*)wgs;
        for (int i = threadIdx.x; i < N_EXP * CDIM / 4; i += blockDim.x)
            dst[i] = src[i];
    }
    __syncthreads();

    int warp  = threadIdx.x >> 5;
    int lane  = threadIdx.x & 31;
    int token = blockIdx.x * 8 + warp;
    if (token >= T) return;

    const float4* xr = (const float4*)(x + (size_t)token * CDIM);

    float acc[N_EXP];
#pragma unroll
    for (int e = 0; e < N_EXP; e++) acc[e] = 0.f;

#pragma unroll
    for (int it = 0; it < CDIM / 128; it++) {          // 8 iterations
        int c4 = it * 32 + lane;
        float4 xv = xr[c4];
#pragma unroll
        for (int e = 0; e < N_EXP; e++) {
            float4 w = *(const float4*)&wgs[e * CDIM + c4 * 4];
            acc[e] += xv.x * w.x + xv.y * w.y + xv.z * w.z + xv.w * w.w;
        }
    }
#pragma unroll
    for (int e = 0; e < N_EXP; e++) {
#pragma unroll
        for (int o = 16; o > 0; o >>= 1)
            acc[e] += __shfl_xor_sync(0xffffffffu, acc[e], o);
    }

    if (lane == 0) {
        int e1 = 0; float l1 = acc[0];
#pragma unroll
        for (int e = 1; e < N_EXP; e++)
            if (acc[e] > l1) { l1 = acc[e]; e1 = e; }
        int e2 = -1; float l2 = -INFINITY;
#pragma unroll
        for (int e = 0; e < N_EXP; e++)
            if (e != e1 && acc[e] > l2) { l2 = acc[e]; e2 = e; }

        float p1 = 1.f / (1.f + expf(l2 - l1));   // stable: l2 <= l1
        float p2 = 1.f - p1;

        g_e1[token] = e1; g_e2[token] = e2;
        g_p1[token] = p1; g_p2[token] = p2;
    }
}

// ---------------------------------------------------------------------------
// Kernel 2: k-major cumulative ranks + used_capacity. One block, 256 threads.
// Writes only the tiny g_r arrays (L2-resident) — no scattered DRAM traffic.
// Ordering: all k=0 assignments (token order), then all k=1 assignments.
// ---------------------------------------------------------------------------
__global__ void rank_kernel(int T, int cap, float* __restrict__ out_used)
{
    __shared__ int s1[NCH][N_EXP + 1];
    __shared__ int s2[NCH][N_EXP + 1];
    __shared__ int tot1[N_EXP], tot2[N_EXP];

    int tid  = threadIdx.x;
    int per  = (T + NCH - 1) / NCH;
    int base = tid * per;
    int end  = min(base + per, T);

    int c1[N_EXP], c2[N_EXP];
#pragma unroll
    for (int e = 0; e < N_EXP; e++) { c1[e] = 0; c2[e] = 0; }
    for (int t = base; t < end; t++) { c1[g_e1[t]]++; c2[g_e2[t]]++; }
#pragma unroll
    for (int e = 0; e < N_EXP; e++) { s1[tid][e] = c1[e]; s2[tid][e] = c2[e]; }
    __syncthreads();

    // warp w: exclusive scan over the 256 chunk-counts of expert w
    int wid = tid >> 5, lane = tid & 31;
    if (wid < N_EXP) {
        int v1[8], v2[8];
        int sum1 = 0, sum2 = 0;
#pragma unroll
        for (int j = 0; j < 8; j++) {
            int idx = lane * 8 + j;
            v1[j] = sum1; sum1 += s1[idx][wid];
            v2[j] = sum2; sum2 += s2[idx][wid];
        }
        int inc1 = sum1, inc2 = sum2;
#pragma unroll
        for (int o = 1; o < 32; o <<= 1) {
            int a = __shfl_up_sync(0xffffffffu, inc1, o);
            int b = __shfl_up_sync(0xffffffffu, inc2, o);
            if (lane >= o) { inc1 += a; inc2 += b; }
        }
        int exc1 = inc1 - sum1, exc2 = inc2 - sum2;
#pragma unroll
        for (int j = 0; j < 8; j++) {
            int idx = lane * 8 + j;
            s1[idx][wid] = exc1 + v1[j];
            s2[idx][wid] = exc2 + v2[j];
        }
        if (lane == 31) { tot1[wid] = inc1; tot2[wid] = inc2; }
    }
    __syncthreads();

    if (tid < N_EXP)
        out_used[tid] = (float)min(tot1[tid] + tot2[tid], cap);

    int o1[N_EXP], o2[N_EXP];
#pragma unroll
    for (int e = 0; e < N_EXP; e++) {
        o1[e] = s1[tid][e];
        o2[e] = tot1[e] + s2[tid][e];     // k=1 ranks start after all k=0
    }
    for (int t = base; t < end; t++) {
        int e = g_e1[t]; g_r1[t] = o1[e]; o1[e]++;
        e     = g_e2[t]; g_r2[t] = o2[e]; o2[e]++;
    }
}

// ---------------------------------------------------------------------------
// Kernel 3: parallel scatter — one thread per token, <=2 (weight, mask)
// pairs. 8192 independent misses in flight across 128 warps.
// ---------------------------------------------------------------------------
__global__ void scatter_kernel(float* __restrict__ cb,
                               float* __restrict__ mask,
                               int T, int cap)
{
    int t = blockIdx.x * blockDim.x + threadIdx.x;
    if (t >= T) return;
    size_t row = (size_t)t * N_EXP * cap;

    int r1 = g_r1[t];
    if (r1 < cap) {
        float p = g_p1[t];
        size_t o = row + (size_t)g_e1[t] * cap + r1;
        cb[o] = p;
        if (p != 0.f) mask[o] = 1.f;
    }
    int r2 = g_r2[t];
    if (r2 < cap) {
        float p = g_p2[t];
        size_t o = row + (size_t)g_e2[t] * cap + r2;
        cb[o] = p;
        if (p != 0.f) mask[o] = 1.f;
    }
}

// ---------------------------------------------------------------------------
extern "C" void kernel_launch(void* const* d_in, const int* in_sizes, int n_in,
                              void* d_out, int out_size)
{
    const float* x  = (const float*)d_in[0];
    const float* wg = (const float*)d_in[1];

    int T = in_sizes[0] / CDIM;                       // 4096
    // out layout: [used_capacity(8) | cb_weight(T*E*cap) | sec_mask(T*E*cap)]
    long long rest = (long long)out_size - N_EXP;
    int cap = (int)(rest / (2LL * T * N_EXP));        // 2048

    float* out_used = (float*)d_out;
    float* cb       = out_used + N_EXP;
    float* mask     = cb + (size_t)T * N_EXP * cap;

    int ngate = (T + 7) / 8;
    fused_gate_fill_kernel<<<ngate + NFILL, 256>>>(
        x, wg, (float*)d_out, T, (size_t)out_size, ngate);

    rank_kernel<<<1, NCH>>>(T, cap, out_used);
    scatter_kernel<<<(T + 255) / 256, 256>>>(cb, mask, T, cap);
}

// round 5
// speedup vs baseline: 1.4912x; 1.0128x over previous
#include <cuda_runtime.h>
#include <math.h>

#define N_EXP 8
#define CDIM  1024
#define MAX_T 8192
#define NCH   256    // rank-scan chunks (threads in rank kernel)
#define NFILL 2048   // fill blocks

// scratch (no allocation allowed -> __device__ globals)
__device__ float g_p1[MAX_T];
__device__ float g_p2[MAX_T];
__device__ int   g_e1[MAX_T];
__device__ int   g_e2[MAX_T];
__device__ int   g_r1[MAX_T];
__device__ int   g_r2[MAX_T];

// ---------------------------------------------------------------------------
// Kernel 1 (fused): blocks [0, ngate) do gating GEMV + top-2 + softmax;
// blocks [ngate, ngate+NFILL) zero-fill the whole output flat.
// Gate work hides entirely under the ~86us fill.
// ---------------------------------------------------------------------------
__global__ void fused_gate_fill_kernel(const float* __restrict__ x,
                                       const float* __restrict__ wg,
                                       float* __restrict__ out,
                                       int T, size_t out_elems, int ngate)
{
    if ((int)blockIdx.x >= ngate) {
        // ------------------ flat zero-fill ------------------
        size_t n4     = out_elems >> 2;
        size_t idx    = (size_t)(blockIdx.x - ngate) * blockDim.x + threadIdx.x;
        size_t stride = (size_t)NFILL * blockDim.x;
        float4* o4 = (float4*)out;
        const float4 z = make_float4(0.f, 0.f, 0.f, 0.f);

        size_t i = idx;
        for (; i + 3 * stride < n4; i += 4 * stride) {
            o4[i]              = z;
            o4[i + stride]     = z;
            o4[i + 2 * stride] = z;
            o4[i + 3 * stride] = z;
        }
        for (; i < n4; i += stride) o4[i] = z;

        // scalar tail (out_elems not multiple of 4)
        if (blockIdx.x == (unsigned)ngate) {
            size_t tail = n4 << 2;
            size_t rem  = out_elems - tail;
            if (threadIdx.x < rem) out[tail + threadIdx.x] = 0.f;
        }
        return;
    }

    // ------------------ gating (warp per token) ------------------
    __shared__ float wgs[N_EXP * CDIM];   // 32 KB
    {
        const float4* src = (const float4*)wg;
        float4*       dst = (float4*)wgs;
        for (int i = threadIdx.x; i < N_EXP * CDIM / 4; i += blockDim.x)
            dst[i] = src[i];
    }
    __syncthreads();

    int warp  = threadIdx.x >> 5;
    int lane  = threadIdx.x & 31;
    int token = blockIdx.x * 8 + warp;
    if (token >= T) return;

    const float4* xr = (const float4*)(x + (size_t)token * CDIM);

    float acc[N_EXP];
#pragma unroll
    for (int e = 0; e < N_EXP; e++) acc[e] = 0.f;

#pragma unroll
    for (int it = 0; it < CDIM / 128; it++) {          // 8 iterations
        int c4 = it * 32 + lane;
        float4 xv = xr[c4];
#pragma unroll
        for (int e = 0; e < N_EXP; e++) {
            float4 w = *(const float4*)&wgs[e * CDIM + c4 * 4];
            acc[e] += xv.x * w.x + xv.y * w.y + xv.z * w.z + xv.w * w.w;
        }
    }
#pragma unroll
    for (int e = 0; e < N_EXP; e++) {
#pragma unroll
        for (int o = 16; o > 0; o >>= 1)
            acc[e] += __shfl_xor_sync(0xffffffffu, acc[e], o);
    }

    if (lane == 0) {
        int e1 = 0; float l1 = acc[0];
#pragma unroll
        for (int e = 1; e < N_EXP; e++)
            if (acc[e] > l1) { l1 = acc[e]; e1 = e; }
        int e2 = -1; float l2 = -INFINITY;
#pragma unroll
        for (int e = 0; e < N_EXP; e++)
            if (e != e1 && acc[e] > l2) { l2 = acc[e]; e2 = e; }

        float p1 = 1.f / (1.f + expf(l2 - l1));   // stable: l2 <= l1
        float p2 = 1.f - p1;

        g_e1[token] = e1; g_e2[token] = e2;
        g_p1[token] = p1; g_p2[token] = p2;
    }
}

// ---------------------------------------------------------------------------
// Kernel 2: k-major cumulative ranks + used_capacity. One block, 256 threads.
// ALL dynamically-indexed per-thread state lives in shared memory (s1/s2
// rows) — no local-memory spills. Ordering: all k=0 assignments (token
// order), then all k=1 assignments.
// ---------------------------------------------------------------------------
__global__ void rank_kernel(int T, int cap, float* __restrict__ out_used)
{
    __shared__ int s1[NCH][N_EXP + 1];
    __shared__ int s2[NCH][N_EXP + 1];
    __shared__ int tot1[N_EXP], tot2[N_EXP];

    int tid  = threadIdx.x;
    int per  = (T + NCH - 1) / NCH;
    int base = tid * per;
    int end  = min(base + per, T);

    // zero my count row, then count directly in smem (dynamic index = LDS/STS)
#pragma unroll
    for (int e = 0; e < N_EXP; e++) { s1[tid][e] = 0; s2[tid][e] = 0; }
    for (int t = base; t < end; t++) {
        s1[tid][g_e1[t]]++;
        s2[tid][g_e2[t]]++;
    }
    __syncthreads();

    // warp w: exclusive scan over the 256 chunk-counts of expert w
    int wid = tid >> 5, lane = tid & 31;
    if (wid < N_EXP) {
        int v1[8], v2[8];
        int sum1 = 0, sum2 = 0;
#pragma unroll
        for (int j = 0; j < 8; j++) {
            int idx = lane * 8 + j;
            v1[j] = sum1; sum1 += s1[idx][wid];
            v2[j] = sum2; sum2 += s2[idx][wid];
        }
        int inc1 = sum1, inc2 = sum2;
#pragma unroll
        for (int o = 1; o < 32; o <<= 1) {
            int a = __shfl_up_sync(0xffffffffu, inc1, o);
            int b = __shfl_up_sync(0xffffffffu, inc2, o);
            if (lane >= o) { inc1 += a; inc2 += b; }
        }
        int exc1 = inc1 - sum1, exc2 = inc2 - sum2;
#pragma unroll
        for (int j = 0; j < 8; j++) {
            int idx = lane * 8 + j;
            s1[idx][wid] = exc1 + v1[j];
            s2[idx][wid] = exc2 + v2[j];
        }
        if (lane == 31) { tot1[wid] = inc1; tot2[wid] = inc2; }
    }
    __syncthreads();

    if (tid < N_EXP)
        out_used[tid] = (float)min(tot1[tid] + tot2[tid], cap);

    // shift k=1 start offsets by total k=0 counts (in smem, no local arrays)
#pragma unroll
    for (int e = 0; e < N_EXP; e++) s2[tid][e] += tot1[e];
    __syncthreads();   // tot1 read before any further writes (defensive)

    // replay: increment my smem offset rows in place, write ranks to global
    for (int t = base; t < end; t++) {
        int e = g_e1[t]; g_r1[t] = s1[tid][e]++;
        e     = g_e2[t]; g_r2[t] = s2[tid][e]++;
    }
}

// ---------------------------------------------------------------------------
// Kernel 3: parallel scatter — one thread per token, <=2 (weight, mask)
// pairs. 8192 independent misses in flight across many warps.
// ---------------------------------------------------------------------------
__global__ void scatter_kernel(float* __restrict__ cb,
                               float* __restrict__ mask,
                               int T, int cap)
{
    int t = blockIdx.x * blockDim.x + threadIdx.x;
    if (t >= T) return;
    size_t row = (size_t)t * N_EXP * cap;

    int r1 = g_r1[t];
    if (r1 < cap) {
        float p = g_p1[t];
        size_t o = row + (size_t)g_e1[t] * cap + r1;
        cb[o] = p;
        if (p != 0.f) mask[o] = 1.f;
    }
    int r2 = g_r2[t];
    if (r2 < cap) {
        float p = g_p2[t];
        size_t o = row + (size_t)g_e2[t] * cap + r2;
        cb[o] = p;
        if (p != 0.f) mask[o] = 1.f;
    }
}

// ---------------------------------------------------------------------------
extern "C" void kernel_launch(void* const* d_in, const int* in_sizes, int n_in,
                              void* d_out, int out_size)
{
    const float* x  = (const float*)d_in[0];
    const float* wg = (const float*)d_in[1];

    int T = in_sizes[0] / CDIM;                       // 4096
    // out layout: [used_capacity(8) | cb_weight(T*E*cap) | sec_mask(T*E*cap)]
    long long rest = (long long)out_size - N_EXP;
    int cap = (int)(rest / (2LL * T * N_EXP));        // 2048

    float* out_used = (float*)d_out;
    float* cb       = out_used + N_EXP;
    float* mask     = cb + (size_t)T * N_EXP * cap;

    int ngate = (T + 7) / 8;
    fused_gate_fill_kernel<<<ngate + NFILL, 256>>>(
        x, wg, (float*)d_out, T, (size_t)out_size, ngate);

    rank_kernel<<<1, NCH>>>(T, cap, out_used);
    scatter_kernel<<<(T + 255) / 256, 256>>>(cb, mask, T, cap);
}